// round 1
// baseline (speedup 1.0000x reference)
#include <cuda_runtime.h>
#include <float.h>

// ROI max pooling, exact integer-bin partition (matches reference):
//   cell (py,px) of roi (y0,x0,h,w) covers rows [y0 + py*h/7, y0 + (py+1)*h/7)
//   and cols [x0 + px*w/7, x0 + (px+1)*w/7). h,w >= 7 so cells are non-empty.
//
// Shapes: feature_map [B=2, H=38, W=38, C=512] f32, rois [B=2, N=64, 4] i32,
// out [B, N, 7, 7, C] f32.
//
// Layout: grid.x = B*N*49 cells, 128 threads/block, thread c owns channels
// [4c, 4c+4) via float4. Each pixel row of C=512 floats = 2048B = one fully
// coalesced block-wide float4 read.

#define H_DIM 38
#define W_DIM 38
#define C4 128           // C/4 float4 groups per pixel
#define POOL 7

__global__ __launch_bounds__(128) void roi_pool_kernel(
    const float4* __restrict__ fm,   // [B, H, W, C/4] as float4
    const int*    __restrict__ rois, // [B*N, 4] (y, x, h, w)
    float4*       __restrict__ out,  // [B*N, 49, C/4] as float4
    int n_per_b)                     // N (rois per batch)
{
    const int cell = blockIdx.x;        // roi*49 + py*7 + px
    const int px   = cell % POOL;
    const int py   = (cell / POOL) % POOL;
    const int roi  = cell / (POOL * POOL);
    const int b    = roi / n_per_b;

    const int4 r = __ldg((const int4*)(rois + roi * 4));
    const int y0 = r.x, x0 = r.y, h = r.z, w = r.w;

    const int ys = y0 + (py * h) / POOL;
    const int ye = y0 + ((py + 1) * h) / POOL;
    const int xs = x0 + (px * w) / POOL;
    const int xe = x0 + ((px + 1) * w) / POOL;

    const int c = threadIdx.x;          // 0..127
    const float4* base = fm + ((size_t)b * H_DIM * W_DIM) * C4;

    float4 m = make_float4(-FLT_MAX, -FLT_MAX, -FLT_MAX, -FLT_MAX);

    for (int y = ys; y < ye; ++y) {
        const float4* row = base + ((size_t)(y * W_DIM)) * C4 + c;
        for (int x = xs; x < xe; ++x) {
            float4 v = __ldg(row + (size_t)x * C4);
            m.x = fmaxf(m.x, v.x);
            m.y = fmaxf(m.y, v.y);
            m.z = fmaxf(m.z, v.z);
            m.w = fmaxf(m.w, v.w);
        }
    }

    out[(size_t)cell * C4 + c] = m;
}

extern "C" void kernel_launch(void* const* d_in, const int* in_sizes, int n_in,
                              void* d_out, int out_size) {
    const float4* fm   = (const float4*)d_in[0];
    const int*    rois = (const int*)d_in[1];
    float4*       out  = (float4*)d_out;

    const int n_rois  = in_sizes[1] / 4;     // B*N = 128
    const int B       = 2;                   // fixed per problem shapes
    const int n_per_b = n_rois / B;          // N = 64

    const int grid = n_rois * POOL * POOL;   // 6272 cells
    roi_pool_kernel<<<grid, 128>>>(fm, rois, out, n_per_b);
}

// round 2
// speedup vs baseline: 1.1382x; 1.1382x over previous
#include <cuda_runtime.h>
#include <float.h>

// ROI max pooling, exact integer-bin partition (matches reference):
//   cell (py,px) of roi (y0,x0,h,w) covers rows [y0 + py*h/7, y0 + (py+1)*h/7)
//   and cols [x0 + px*w/7, x0 + (px+1)*w/7). h,w >= 7 so cells are non-empty.
//
// Shapes: feature_map [B=2, H=38, W=38, C=512] f32, rois [B=2, N=64, 4] i32,
// out [B, N, 7, 7, C] f32.
//
// R1 -> R2: 64-thread blocks, each thread owns 8 channels (2x float4 at
// c and c+64), inner x-loop unrolled by 2 => 4 independent LDG.128 per
// iteration (MLP ~4/warp), ~25% fewer issue slots, finer block granularity
// to smooth the 36:1 per-cell pixel-count imbalance.

#define H_DIM 38
#define W_DIM 38
#define C4 128           // C/4 float4 groups per pixel
#define POOL 7

__device__ __forceinline__ void fmax4(float4& m, const float4 v) {
    m.x = fmaxf(m.x, v.x);
    m.y = fmaxf(m.y, v.y);
    m.z = fmaxf(m.z, v.z);
    m.w = fmaxf(m.w, v.w);
}

__global__ __launch_bounds__(64) void roi_pool_kernel(
    const float4* __restrict__ fm,   // [B, H, W, C/4] as float4
    const int*    __restrict__ rois, // [B*N, 4] (y, x, h, w)
    float4*       __restrict__ out,  // [B*N, 49, C/4] as float4
    int n_per_b)                     // N (rois per batch)
{
    const int cell = blockIdx.x;        // roi*49 + py*7 + px
    const int px   = cell % POOL;
    const int py   = (cell / POOL) % POOL;
    const int roi  = cell / (POOL * POOL);
    const int b    = roi / n_per_b;

    const int4 r = __ldg((const int4*)(rois + roi * 4));
    const int y0 = r.x, x0 = r.y, h = r.z, w = r.w;

    const int ys = y0 + (py * h) / POOL;
    const int ye = y0 + ((py + 1) * h) / POOL;
    const int xs = x0 + (px * w) / POOL;
    const int xe = x0 + ((px + 1) * w) / POOL;

    const int c = threadIdx.x;          // 0..63, owns float4 slots c and c+64
    const float4* base = fm + ((size_t)b * H_DIM * W_DIM) * C4 + c;

    float4 m0 = make_float4(-FLT_MAX, -FLT_MAX, -FLT_MAX, -FLT_MAX);
    float4 m1 = m0;

    for (int y = ys; y < ye; ++y) {
        const float4* p = base + ((size_t)(y * W_DIM + xs)) * C4;
        int x = xs;
        // unroll-by-2: 4 independent LDG.128 in flight before the max chain
        for (; x + 1 < xe; x += 2, p += 2 * C4) {
            float4 a0 = __ldg(p);
            float4 a1 = __ldg(p + 64);
            float4 b0 = __ldg(p + C4);
            float4 b1 = __ldg(p + C4 + 64);
            fmax4(m0, a0);
            fmax4(m1, a1);
            fmax4(m0, b0);
            fmax4(m1, b1);
        }
        if (x < xe) {
            float4 a0 = __ldg(p);
            float4 a1 = __ldg(p + 64);
            fmax4(m0, a0);
            fmax4(m1, a1);
        }
    }

    float4* o = out + (size_t)cell * C4 + c;
    o[0]  = m0;
    o[64] = m1;
}

extern "C" void kernel_launch(void* const* d_in, const int* in_sizes, int n_in,
                              void* d_out, int out_size) {
    const float4* fm   = (const float4*)d_in[0];
    const int*    rois = (const int*)d_in[1];
    float4*       out  = (float4*)d_out;

    const int n_rois  = in_sizes[1] / 4;     // B*N = 128
    const int B       = 2;                   // fixed per problem shapes
    const int n_per_b = n_rois / B;          // N = 64

    const int grid = n_rois * POOL * POOL;   // 6272 cells
    roi_pool_kernel<<<grid, 64>>>(fm, rois, out, n_per_b);
}

// round 4
// speedup vs baseline: 1.3142x; 1.1546x over previous
#include <cuda_runtime.h>
#include <float.h>

// ROI max pooling, exact integer-bin partition (matches reference):
//   cell (py,px) of roi (y0,x0,h,w) covers rows [y0 + py*h/7, y0 + (py+1)*h/7)
//   and cols [x0 + px*w/7, x0 + (px+1)*w/7). h,w >= 7 so cells are non-empty.
//
// Shapes: feature_map [B=2, H=38, W=38, C=512] f32, rois [B=2, N=64, 4] i32,
// out [B, N, 7, 7, C] f32.
//
// R2 -> R3: latency-bound (nothing saturated: L1 35%, L2 37%, issue 37%).
// Unroll y by 2 in addition to x by 2 => 8 independent LDG.128 in flight per
// iteration. Halves exposed load latency per byte and shortens the big-cell
// critical path that sets the imbalance tail (cells are 1x1..6x6 pixels).

#define H_DIM 38
#define W_DIM 38
#define C4 128           // C/4 float4 groups per pixel
#define POOL 7
#define ROWSTRIDE (W_DIM * C4)

__device__ __forceinline__ void fmax4(float4& m, const float4 v) {
    m.x = fmaxf(m.x, v.x);
    m.y = fmaxf(m.y, v.y);
    m.z = fmaxf(m.z, v.z);
    m.w = fmaxf(m.w, v.w);
}

__global__ __launch_bounds__(64) void roi_pool_kernel(
    const float4* __restrict__ fm,   // [B, H, W, C/4] as float4
    const int*    __restrict__ rois, // [B*N, 4] (y, x, h, w)
    float4*       __restrict__ out,  // [B*N, 49, C/4] as float4
    int n_per_b)                     // N (rois per batch)
{
    const int cell = blockIdx.x;        // roi*49 + py*7 + px
    const int px   = cell % POOL;
    const int py   = (cell / POOL) % POOL;
    const int roi  = cell / (POOL * POOL);
    const int b    = roi / n_per_b;

    const int4 r = __ldg((const int4*)(rois + roi * 4));
    const int y0 = r.x, x0 = r.y, h = r.z, w = r.w;

    const int ys = y0 + (py * h) / POOL;
    const int ye = y0 + ((py + 1) * h) / POOL;
    const int xs = x0 + (px * w) / POOL;
    const int xe = x0 + ((px + 1) * w) / POOL;

    const int c = threadIdx.x;          // 0..63, owns float4 slots c and c+64
    const float4* base = fm + ((size_t)b * H_DIM * W_DIM) * C4 + c;

    float4 m0 = make_float4(-FLT_MAX, -FLT_MAX, -FLT_MAX, -FLT_MAX);
    float4 m1 = m0;

    int y = ys;
    // ---- y-unroll 2, x-unroll 2: 8 independent LDG.128 per iteration ----
    for (; y + 1 < ye; y += 2) {
        const float4* p0 = base + ((size_t)(y * W_DIM + xs)) * C4;
        const float4* p1 = p0 + ROWSTRIDE;
        int x = xs;
        for (; x + 1 < xe; x += 2, p0 += 2 * C4, p1 += 2 * C4) {
            float4 a0 = __ldg(p0);
            float4 a1 = __ldg(p0 + 64);
            float4 a2 = __ldg(p0 + C4);
            float4 a3 = __ldg(p0 + C4 + 64);
            float4 b0 = __ldg(p1);
            float4 b1 = __ldg(p1 + 64);
            float4 b2 = __ldg(p1 + C4);
            float4 b3 = __ldg(p1 + C4 + 64);
            fmax4(m0, a0); fmax4(m1, a1);
            fmax4(m0, a2); fmax4(m1, a3);
            fmax4(m0, b0); fmax4(m1, b1);
            fmax4(m0, b2); fmax4(m1, b3);
        }
        if (x < xe) {
            float4 a0 = __ldg(p0);
            float4 a1 = __ldg(p0 + 64);
            float4 b0 = __ldg(p1);
            float4 b1 = __ldg(p1 + 64);
            fmax4(m0, a0); fmax4(m1, a1);
            fmax4(m0, b0); fmax4(m1, b1);
        }
    }
    // ---- remainder row (odd cell height), x-unroll 2 ----
    if (y < ye) {
        const float4* p0 = base + ((size_t)(y * W_DIM + xs)) * C4;
        int x = xs;
        for (; x + 1 < xe; x += 2, p0 += 2 * C4) {
            float4 a0 = __ldg(p0);
            float4 a1 = __ldg(p0 + 64);
            float4 a2 = __ldg(p0 + C4);
            float4 a3 = __ldg(p0 + C4 + 64);
            fmax4(m0, a0); fmax4(m1, a1);
            fmax4(m0, a2); fmax4(m1, a3);
        }
        if (x < xe) {
            float4 a0 = __ldg(p0);
            float4 a1 = __ldg(p0 + 64);
            fmax4(m0, a0); fmax4(m1, a1);
        }
    }

    float4* o = out + (size_t)cell * C4 + c;
    o[0]  = m0;
    o[64] = m1;
}

extern "C" void kernel_launch(void* const* d_in, const int* in_sizes, int n_in,
                              void* d_out, int out_size) {
    const float4* fm   = (const float4*)d_in[0];
    const int*    rois = (const int*)d_in[1];
    float4*       out  = (float4*)d_out;

    const int n_rois  = in_sizes[1] / 4;     // B*N = 128
    const int B       = 2;                   // fixed per problem shapes
    const int n_per_b = n_rois / B;          // N = 64

    const int grid = n_rois * POOL * POOL;   // 6272 cells
    roi_pool_kernel<<<grid, 64>>>(fm, rois, out, n_per_b);
}

// round 8
// speedup vs baseline: 1.3208x; 1.0050x over previous
#include <cuda_runtime.h>
#include <float.h>

// ROI max pooling, exact integer-bin partition (matches reference):
//   cell (py,px) of roi (y0,x0,h,w) covers rows [y0 + py*h/7, y0 + (py+1)*h/7)
//   and cols [x0 + px*w/7, x0 + (px+1)*w/7). h,w >= 7 so cells are non-empty.
//
// Shapes: feature_map [B=2, H=38, W=38, C=512] f32, rois [B=2, N=64, 4] i32,
// out [B, N, 7, 7, C] f32.
//
// R3 -> R4: imbalance/latency bound (occ 42%, issue 30%, L1/L2 ~35%; L1
// throughput floor is ~4us). Split channels across 2 blocks and use 1-warp
// (32-thread) blocks: grid 6272 -> 12544, each thread still owns 2 float4
// (ILP of 8 in-flight LDG.128 preserved), big-cell critical path halves,
// scheduling granularity 2x finer -> smaller tail.

#define H_DIM 38
#define W_DIM 38
#define C4 128           // C/4 float4 groups per pixel
#define POOL 7
#define ROWSTRIDE (W_DIM * C4)

__device__ __forceinline__ void fmax4(float4& m, const float4 v) {
    m.x = fmaxf(m.x, v.x);
    m.y = fmaxf(m.y, v.y);
    m.z = fmaxf(m.z, v.z);
    m.w = fmaxf(m.w, v.w);
}

__global__ __launch_bounds__(32) void roi_pool_kernel(
    const float4* __restrict__ fm,   // [B, H, W, C/4] as float4
    const int*    __restrict__ rois, // [B*N, 4] (y, x, h, w)
    float4*       __restrict__ out,  // [B*N, 49, C/4] as float4
    int n_per_b)                     // N (rois per batch)
{
    const int cell = blockIdx.x;        // roi*49 + py*7 + px
    const int px   = cell % POOL;
    const int py   = (cell / POOL) % POOL;
    const int roi  = cell / (POOL * POOL);
    const int b    = roi / n_per_b;

    const int4 r = __ldg((const int4*)(rois + roi * 4));
    const int y0 = r.x, x0 = r.y, h = r.z, w = r.w;

    const int ys = y0 + (py * h) / POOL;
    const int ye = y0 + ((py + 1) * h) / POOL;
    const int xs = x0 + (px * w) / POOL;
    const int xe = x0 + ((px + 1) * w) / POOL;

    // channel half: block gy handles float4 slots [gy*64, gy*64+64)
    // thread t owns slots gy*64 + t and gy*64 + t + 32 (each warp-LDG reads
    // 32 contiguous float4 = 512B, fully coalesced)
    const int c = (blockIdx.y << 6) + threadIdx.x;
    const float4* base = fm + ((size_t)b * H_DIM * W_DIM) * C4 + c;

    float4 m0 = make_float4(-FLT_MAX, -FLT_MAX, -FLT_MAX, -FLT_MAX);
    float4 m1 = m0;

    int y = ys;
    // ---- y-unroll 2, x-unroll 2: 8 independent LDG.128 per iteration ----
    for (; y + 1 < ye; y += 2) {
        const float4* p0 = base + ((size_t)(y * W_DIM + xs)) * C4;
        const float4* p1 = p0 + ROWSTRIDE;
        int x = xs;
        for (; x + 1 < xe; x += 2, p0 += 2 * C4, p1 += 2 * C4) {
            float4 a0 = __ldg(p0);
            float4 a1 = __ldg(p0 + 32);
            float4 a2 = __ldg(p0 + C4);
            float4 a3 = __ldg(p0 + C4 + 32);
            float4 b0 = __ldg(p1);
            float4 b1 = __ldg(p1 + 32);
            float4 b2 = __ldg(p1 + C4);
            float4 b3 = __ldg(p1 + C4 + 32);
            fmax4(m0, a0); fmax4(m1, a1);
            fmax4(m0, a2); fmax4(m1, a3);
            fmax4(m0, b0); fmax4(m1, b1);
            fmax4(m0, b2); fmax4(m1, b3);
        }
        if (x < xe) {
            float4 a0 = __ldg(p0);
            float4 a1 = __ldg(p0 + 32);
            float4 b0 = __ldg(p1);
            float4 b1 = __ldg(p1 + 32);
            fmax4(m0, a0); fmax4(m1, a1);
            fmax4(m0, b0); fmax4(m1, b1);
        }
    }
    // ---- remainder row (odd cell height), x-unroll 2 ----
    if (y < ye) {
        const float4* p0 = base + ((size_t)(y * W_DIM + xs)) * C4;
        int x = xs;
        for (; x + 1 < xe; x += 2, p0 += 2 * C4) {
            float4 a0 = __ldg(p0);
            float4 a1 = __ldg(p0 + 32);
            float4 a2 = __ldg(p0 + C4);
            float4 a3 = __ldg(p0 + C4 + 32);
            fmax4(m0, a0); fmax4(m1, a1);
            fmax4(m0, a2); fmax4(m1, a3);
        }
        if (x < xe) {
            float4 a0 = __ldg(p0);
            float4 a1 = __ldg(p0 + 32);
            fmax4(m0, a0); fmax4(m1, a1);
        }
    }

    float4* o = out + (size_t)cell * C4 + c;
    o[0]  = m0;
    o[32] = m1;
}

extern "C" void kernel_launch(void* const* d_in, const int* in_sizes, int n_in,
                              void* d_out, int out_size) {
    const float4* fm   = (const float4*)d_in[0];
    const int*    rois = (const int*)d_in[1];
    float4*       out  = (float4*)d_out;

    const int n_rois  = in_sizes[1] / 4;     // B*N = 128
    const int B       = 2;                   // fixed per problem shapes
    const int n_per_b = n_rois / B;          // N = 64

    dim3 grid(n_rois * POOL * POOL, 2);      // 6272 cells x 2 channel halves
    roi_pool_kernel<<<grid, 32>>>(fm, rois, out, n_per_b);
}